// round 1
// baseline (speedup 1.0000x reference)
#include <cuda_runtime.h>
#include <math.h>

#define NSEG 50000
#define MROWS 800000
#define DDIM 128
#define KDIM 256   // 2*DDIM
#define ODIM 128

// Scratch (no allocations allowed in kernel_launch)
__device__ int   g_starts[NSEG + 1];
__device__ float g_pooled[(long long)NSEG * KDIM];

// ---------------------------------------------------------------------------
// Kernel 1: segment boundary detection. ids are sorted and every segment id
// in [0, NSEG) occurs at least once, so starts are well-defined.
// Dtype probe: if ids are int64, word [MROWS-1] is the high half of an
// element (always 0 since ids < 2^31). If int32, it's seg[M-1] == NSEG-1 != 0.
// ---------------------------------------------------------------------------
__global__ void boundary_kernel(const void* __restrict__ segraw) {
    int i = blockIdx.x * blockDim.x + threadIdx.x;
    if (i >= MROWS) return;
    const int* s32 = (const int*)segraw;
    bool is64 = (s32[MROWS - 1] == 0);
    int s, prev;
    if (is64) {
        const long long* s64 = (const long long*)segraw;
        s = (int)s64[i];
        prev = (i > 0) ? (int)s64[i - 1] : -1;
    } else {
        s = s32[i];
        prev = (i > 0) ? s32[i - 1] : -1;
    }
    if (s != prev) g_starts[s] = i;
    if (i == 0) g_starts[NSEG] = MROWS;
}

// ---------------------------------------------------------------------------
// Kernel 2: segmented max + mean pooling. One warp per segment; each lane owns
// one float4 (4 dims) of the 128-dim row -> a warp reads a full 512B row per
// iteration, perfectly coalesced, streaming lane_encoding exactly once.
// pooled[n][0:128] = max, pooled[n][128:256] = mean.
// ---------------------------------------------------------------------------
__global__ void pool_kernel(const float* __restrict__ lane) {
    int warp = threadIdx.x >> 5;
    int lid  = threadIdx.x & 31;
    int n = blockIdx.x * 4 + warp;
    if (n >= NSEG) return;
    int start = g_starts[n];
    int end   = g_starts[n + 1];

    const float4* p = reinterpret_cast<const float4*>(lane) + (long long)start * 32 + lid;
    float4 mx = make_float4(-INFINITY, -INFINITY, -INFINITY, -INFINITY);
    float4 sm = make_float4(0.f, 0.f, 0.f, 0.f);

    for (int r = start; r < end; ++r, p += 32) {
        float4 v = *p;
        mx.x = fmaxf(mx.x, v.x); sm.x += v.x;
        mx.y = fmaxf(mx.y, v.y); sm.y += v.y;
        mx.z = fmaxf(mx.z, v.z); sm.z += v.z;
        mx.w = fmaxf(mx.w, v.w); sm.w += v.w;
    }
    float inv = 1.0f / (float)(end - start);
    float4* o = reinterpret_cast<float4*>(g_pooled + (long long)n * KDIM);
    o[lid] = mx;
    o[32 + lid] = make_float4(sm.x * inv, sm.y * inv, sm.z * inv, sm.w * inv);
}

// ---------------------------------------------------------------------------
// Kernel 3: out = relu(pooled @ W^T + b), fp32 with packed f32x2 FMA.
// BM=128, BN=64, BK=32, 256 threads (16x16), micro-tile 8 rows x 4 cols
// (= 8x2 f32x2 accumulators). ptxas never emits FFMA2 from C++, so we use
// inline PTX fma.rn.f32x2 to get the full 128 fp32 FMA/cyc/SM rate.
// ---------------------------------------------------------------------------
#define BM 128
#define BN 64
#define BK 32
#define TM 8
#define TN 4

__device__ __forceinline__ unsigned long long pack2(float x, float y) {
    unsigned long long r;
    asm("mov.b64 %0, {%1, %2};" : "=l"(r) : "f"(x), "f"(y));
    return r;
}
__device__ __forceinline__ void unpack2(unsigned long long v, float& x, float& y) {
    asm("mov.b64 {%0, %1}, %2;" : "=f"(x), "=f"(y) : "l"(v));
}
__device__ __forceinline__ void ffma2(unsigned long long& d,
                                      unsigned long long a,
                                      unsigned long long b) {
    asm("fma.rn.f32x2 %0, %1, %2, %0;" : "+l"(d) : "l"(a), "l"(b));
}

__global__ __launch_bounds__(256) void gemm_kernel(const float* __restrict__ W,
                                                   const float* __restrict__ bias,
                                                   float* __restrict__ out) {
    __shared__ float As[BK][BM];
    __shared__ float Bs[BK][BN];

    const int tid = threadIdx.x;
    const int tx = tid & 15;   // col group: cols tx*4 .. tx*4+3
    const int ty = tid >> 4;   // row group: rows ty*8 .. ty*8+7
    const int bm = blockIdx.x * BM;
    const int bn = blockIdx.y * BN;

    unsigned long long acc[TM][2];
#pragma unroll
    for (int i = 0; i < TM; ++i) { acc[i][0] = 0ull; acc[i][1] = 0ull; }

    for (int kt = 0; kt < KDIM; kt += BK) {
        // Load A tile (BM x BK) transposed into As[k][m]. 1024 float4 total.
#pragma unroll
        for (int i = 0; i < 4; ++i) {
            int idx = tid + i * 256;
            int row = idx >> 3;   // 0..127
            int c4  = idx & 7;    // 0..7  (k/4 within tile)
            float4 v = make_float4(0.f, 0.f, 0.f, 0.f);
            int grow = bm + row;
            if (grow < NSEG)
                v = *(const float4*)&g_pooled[(long long)grow * KDIM + kt + c4 * 4];
            As[c4 * 4 + 0][row] = v.x;
            As[c4 * 4 + 1][row] = v.y;
            As[c4 * 4 + 2][row] = v.z;
            As[c4 * 4 + 3][row] = v.w;
        }
        // Load B tile (BN x BK) transposed into Bs[k][n]. W is [ODIM][KDIM].
#pragma unroll
        for (int i = 0; i < 2; ++i) {
            int idx = tid + i * 256;
            int row = idx >> 3;   // 0..63
            int c4  = idx & 7;
            float4 v = *(const float4*)&W[(long long)(bn + row) * KDIM + kt + c4 * 4];
            Bs[c4 * 4 + 0][row] = v.x;
            Bs[c4 * 4 + 1][row] = v.y;
            Bs[c4 * 4 + 2][row] = v.z;
            Bs[c4 * 4 + 3][row] = v.w;
        }
        __syncthreads();

#pragma unroll
        for (int k = 0; k < BK; ++k) {
            float4 a0 = *(const float4*)&As[k][ty * TM];
            float4 a1 = *(const float4*)&As[k][ty * TM + 4];
            float4 b0 = *(const float4*)&Bs[k][tx * TN];
            unsigned long long bp0 = pack2(b0.x, b0.y);
            unsigned long long bp1 = pack2(b0.z, b0.w);
            float ar[TM] = {a0.x, a0.y, a0.z, a0.w, a1.x, a1.y, a1.z, a1.w};
#pragma unroll
            for (int i = 0; i < TM; ++i) {
                unsigned long long ap = pack2(ar[i], ar[i]);
                ffma2(acc[i][0], ap, bp0);
                ffma2(acc[i][1], ap, bp1);
            }
        }
        __syncthreads();
    }

    // Epilogue: bias + relu, vectorized float4 store.
    const int col = bn + tx * TN;
    float4 bv = *(const float4*)&bias[col];
#pragma unroll
    for (int i = 0; i < TM; ++i) {
        int row = bm + ty * TM + i;
        if (row < NSEG) {
            float x0, x1, x2, x3;
            unpack2(acc[i][0], x0, x1);
            unpack2(acc[i][1], x2, x3);
            float4 r;
            r.x = fmaxf(x0 + bv.x, 0.f);
            r.y = fmaxf(x1 + bv.y, 0.f);
            r.z = fmaxf(x2 + bv.z, 0.f);
            r.w = fmaxf(x3 + bv.w, 0.f);
            *(float4*)&out[(long long)row * ODIM + col] = r;
        }
    }
}

// ---------------------------------------------------------------------------
// Inputs (metadata order): obs_encoding (unused), lane_encoding, same_obs_mask,
// W, b. Output: float32 [NSEG, ODIM].
// ---------------------------------------------------------------------------
extern "C" void kernel_launch(void* const* d_in, const int* in_sizes, int n_in,
                              void* d_out, int out_size) {
    const float* lane = (const float*)d_in[1];
    const void*  seg  = d_in[2];
    const float* W    = (const float*)d_in[3];
    const float* bias = (const float*)d_in[4];
    float* out = (float*)d_out;

    boundary_kernel<<<(MROWS + 255) / 256, 256>>>(seg);
    pool_kernel<<<(NSEG + 3) / 4, 128>>>(lane);
    dim3 grid((NSEG + BM - 1) / BM, ODIM / BN);
    gemm_kernel<<<grid, 256>>>(W, bias, out);
}